// round 10
// baseline (speedup 1.0000x reference)
#include <cuda_runtime.h>
#include <cstdint>

#define NNODES 50000

// ---------------- scratch (__device__ globals; no allocation) ----------------
// g_acc layout: [cnt: N floats][s1: N*96][s2: N*48]  -> single memset target
__device__ float g_acc[(size_t)NNODES * (1 + 96 + 48)];
__device__ float g_xl [(size_t)NNODES * 96];   // x  @ w1_l.T
__device__ float g_h1 [(size_t)NNODES * 96];   // layer-1: self term, then final
__device__ float g_h1l[(size_t)NNODES * 48];   // h1 @ w2_l.T
__device__ float g_wt1[96 * 192];              // transposed combined [k][o] (w1_l | w1_r)
__device__ float g_wt2[96 * 96];               // transposed combined [k][o] (w2_l | w2_r)

// ---------------- atomics ----------------
__device__ __forceinline__ void red_add_v4(float4* p, float4 v) {
    asm volatile("red.global.add.v4.f32 [%0], {%1, %2, %3, %4};"
                 :: "l"(p), "f"(v.x), "f"(v.y), "f"(v.z), "f"(v.w) : "memory");
}
__device__ __forceinline__ void red_add_f(float* p, float v) {
    asm volatile("red.global.add.f32 [%0], %1;" :: "l"(p), "f"(v) : "memory");
}

// ---------------- f32x2 packed FMA (sm_103a; PTX-only) ----------------
__device__ __forceinline__ unsigned long long pack2(float x, float y) {
    unsigned long long r;
    asm("mov.b64 %0, {%1, %2};" : "=l"(r) : "f"(x), "f"(y));
    return r;
}
__device__ __forceinline__ unsigned long long ffma2(unsigned long long a,
                                                    unsigned long long b,
                                                    unsigned long long c) {
    unsigned long long d;
    asm("fma.rn.f32x2 %0, %1, %2, %3;" : "=l"(d) : "l"(a), "l"(b), "l"(c));
    return d;
}

// ---------------- weight pre-transpose (tiny, once per launch) ----------------
__global__ void prep_weights(const float* __restrict__ w1l, const float* __restrict__ w1r,
                             const float* __restrict__ w2l, const float* __restrict__ w2r) {
    int tid = blockIdx.x * blockDim.x + threadIdx.x;
    int stride = blockDim.x * gridDim.x;
    for (int i = tid; i < 96 * 96; i += stride) {
        int o = i / 96, k = i % 96;
        g_wt1[k * 192 + o]      = w1l[i];
        g_wt1[k * 192 + 96 + o] = w1r[i];
    }
    for (int i = tid; i < 48 * 96; i += stride) {
        int o = i / 96, k = i % 96;
        g_wt2[k * 96 + o]      = w2l[i];
        g_wt2[k * 96 + 48 + o] = w2r[i];
    }
}

// ---------------- fused dual-output GEMM with FFMA2 ----------------
// NP = f32x2 pairs per lane (192->3, 96->1); OUT=96 adds one scalar column/lane.
// Pair cols: lane*2*NP + 2j (contiguous -> 64-bit smem loads for W).
// Scalar col (OUT=96): 64*NP + lane (always in outb half).
template<int OUT>
__global__ void gemm_k(const float* __restrict__ xin, const float* __restrict__ wt,
                       const float* __restrict__ bias,
                       float* __restrict__ outa, float* __restrict__ outb, int nrows) {
    constexpr int  NP   = OUT / 64;
    constexpr bool SC   = (OUT % 64) != 0;
    constexpr int  HALF = OUT / 2;
    extern __shared__ float sm[];
    float* wTs = sm;              // 96*OUT
    float* xs  = sm + 96 * OUT;   // 64*96 row-major
    const int tid = threadIdx.x;

    for (int f = tid; f < 96 * OUT / 4; f += 256)
        ((float4*)wTs)[f] = ((const float4*)wt)[f];

    const int row0 = blockIdx.x * 64;
    for (int f = tid; f < 64 * 24; f += 256) {
        int r = f / 24, c = f % 24;
        float4 v = make_float4(0.f, 0.f, 0.f, 0.f);
        if (row0 + r < nrows) v = ((const float4*)xin)[(size_t)(row0 + r) * 24 + c];
        ((float4*)xs)[f] = v;
    }
    __syncthreads();

    const int warp = tid >> 5, lane = tid & 31;
    const int rb = warp * 8;
    const int pc = lane * 2 * NP;

    unsigned long long acc2[8][NP];
    float accs[8];
#pragma unroll
    for (int m = 0; m < 8; m++) {
#pragma unroll
        for (int j = 0; j < NP; j++) acc2[m][j] = 0ull;
        accs[m] = 0.f;
    }

    const float* wp  = wTs + pc;
    const float* wsp = wTs + 64 * NP + lane;

#pragma unroll 2
    for (int k = 0; k < 96; k++) {
        unsigned long long w2[NP];
#pragma unroll
        for (int j = 0; j < NP; j++)
            w2[j] = *(const unsigned long long*)(wp + k * OUT + 2 * j);
        float ws = SC ? wsp[k * OUT] : 0.f;
#pragma unroll
        for (int m = 0; m < 8; m++) {
            float x = xs[(rb + m) * 96 + k];
            unsigned long long x2 = pack2(x, x);
#pragma unroll
            for (int j = 0; j < NP; j++) acc2[m][j] = ffma2(x2, w2[j], acc2[m][j]);
            if (SC) accs[m] = fmaf(x, ws, accs[m]);
        }
    }

#pragma unroll
    for (int m = 0; m < 8; m++) {
        int r = row0 + rb + m;
        if (r >= nrows) break;
#pragma unroll
        for (int j = 0; j < NP; j++) {
            int c = pc + 2 * j;                   // pairs never straddle HALF
            float2 v = *(float2*)&acc2[m][j];
            if (c < HALF) {
                *(float2*)(outa + (size_t)r * HALF + c) = v;
            } else {
                int cb = c - HALF;
                float2 bv = *(const float2*)(bias + cb);
                v.x += bv.x; v.y += bv.y;
                *(float2*)(outb + (size_t)r * HALF + cb) = v;
            }
        }
        if (SC) {
            int cb = 64 * NP + lane - HALF;
            outb[(size_t)r * HALF + cb] = accs[m] + __ldg(&bias[cb]);
        }
    }
}

// ---------------- flat edge scatter (one thread = one (edge, float4-chunk)) ----
// CHUNKS = row float4 count (24 for 96 dims, 12 for 48). 100% lane utilization;
// index loads broadcast within the warp (same line), gathers coalesce per row.
template<int CHUNKS, bool COUNT>
__global__ void scatter_k(const int* __restrict__ ei, int E,
                          const float* __restrict__ feat, float* __restrict__ accv,
                          float* __restrict__ cnt) {
    int g = blockIdx.x * blockDim.x + threadIdx.x;      // < E*CHUNKS (19.2M max)
    int e  = g / CHUNKS;
    int ch = g % CHUNKS;
    if (e >= E) return;
    int s = __ldg(&ei[e]);
    int d = __ldg(&ei[E + e]);
    float4 v = __ldg((const float4*)feat + (size_t)s * CHUNKS + ch);
    red_add_v4((float4*)accv + (size_t)d * CHUNKS + ch, v);
    if (COUNT && ch == 0) red_add_f(cnt + d, 1.0f);
}

// ---------------- finalize ----------------
__global__ void fin1_k(int n) {  // n = N*24 (float4 count over N*96)
    int idx = blockIdx.x * blockDim.x + threadIdx.x;
    if (idx >= n) return;
    int i = idx / 24;
    float inv = 1.0f / fmaxf(g_acc[i], 1.0f);
    const float4* s1 = (const float4*)(g_acc + NNODES);
    float4 s = s1[idx];
    float4 h = ((float4*)g_h1)[idx];
    float4 r;
    r.x = fmaxf(fmaf(s.x, inv, h.x), 0.f);
    r.y = fmaxf(fmaf(s.y, inv, h.y), 0.f);
    r.z = fmaxf(fmaf(s.z, inv, h.z), 0.f);
    r.w = fmaxf(fmaf(s.w, inv, h.w), 0.f);
    ((float4*)g_h1)[idx] = r;
}

__global__ void fin2_k(float* __restrict__ out, int n) {  // n = N*12
    int idx = blockIdx.x * blockDim.x + threadIdx.x;
    if (idx >= n) return;
    int i = idx / 12;
    float inv = 1.0f / fmaxf(g_acc[i], 1.0f);
    const float4* s2 = (const float4*)(g_acc + (size_t)NNODES * 97);
    float4 s = s2[idx];
    float4 o = ((float4*)out)[idx];
    o.x = fmaf(s.x, inv, o.x);
    o.y = fmaf(s.y, inv, o.y);
    o.z = fmaf(s.z, inv, o.z);
    o.w = fmaf(s.w, inv, o.w);
    ((float4*)out)[idx] = o;
}

// ---------------- launch ----------------
extern "C" void kernel_launch(void* const* d_in, const int* in_sizes, int n_in,
                              void* d_out, int out_size) {
    const float* x   = (const float*)d_in[0];
    const int*   ei  = (const int*)d_in[1];     // int32 (JAX x64 disabled)
    const float* w1l = (const float*)d_in[2];
    const float* b1  = (const float*)d_in[3];
    const float* w1r = (const float*)d_in[4];
    const float* w2l = (const float*)d_in[5];
    const float* b2  = (const float*)d_in[6];
    const float* w2r = (const float*)d_in[7];
    float*       out = (float*)d_out;

    const int N = in_sizes[0] / 96;     // 50000
    const int E = in_sizes[1] / 2;      // 800000

    void *p_acc, *p_xl, *p_h1, *p_h1l, *p_wt1, *p_wt2;
    cudaGetSymbolAddress(&p_acc, g_acc);
    cudaGetSymbolAddress(&p_xl,  g_xl);
    cudaGetSymbolAddress(&p_h1,  g_h1);
    cudaGetSymbolAddress(&p_h1l, g_h1l);
    cudaGetSymbolAddress(&p_wt1, g_wt1);
    cudaGetSymbolAddress(&p_wt2, g_wt2);

    float* cnt = (float*)p_acc;
    float* s1  = cnt + NNODES;
    float* s2  = cnt + (size_t)NNODES * 97;

    static bool attr_done = false;
    if (!attr_done) {
        cudaFuncSetAttribute(gemm_k<192>,
                             cudaFuncAttributeMaxDynamicSharedMemorySize,
                             (96 * 192 + 64 * 96) * 4);
        cudaFuncSetAttribute(gemm_k<96>,
                             cudaFuncAttributeMaxDynamicSharedMemorySize,
                             (96 * 96 + 64 * 96) * 4);
        attr_done = true;
    }

    // zero cnt | s1 | s2 in one memset node
    cudaMemsetAsync(p_acc, 0, sizeof(float) * (size_t)NNODES * 145, 0);

    prep_weights<<<64, 256>>>(w1l, w1r, w2l, w2r);

    const int gemm_blocks = (N + 63) / 64;

    // layer 1: xl = x @ w1_l.T ; h1 = x @ w1_r.T + b1
    gemm_k<192><<<gemm_blocks, 256, (96 * 192 + 64 * 96) * 4>>>(
        x, (const float*)p_wt1, b1, (float*)p_xl, (float*)p_h1, N);

    // s1 += xl[src] per edge; cnt[dst] += 1
    scatter_k<24, true><<<(E * 24 + 255) / 256, 256>>>(ei, E, (const float*)p_xl, s1, cnt);

    // h1 = relu(s1/cnt + h1)
    fin1_k<<<(N * 24 + 255) / 256, 256>>>(N * 24);

    // layer 2: h1l = h1 @ w2_l.T ; out = h1 @ w2_r.T + b2
    gemm_k<96><<<gemm_blocks, 256, (96 * 96 + 64 * 96) * 4>>>(
        (const float*)p_h1, (const float*)p_wt2, b2, (float*)p_h1l, out, N);

    // s2 += h1l[src] per edge
    scatter_k<12, false><<<(E * 12 + 255) / 256, 256>>>(ei, E, (const float*)p_h1l, s2, nullptr);

    // out += s2/cnt
    fin2_k<<<(N * 12 + 255) / 256, 256>>>(out, N * 12);
}

// round 12
// speedup vs baseline: 1.5879x; 1.5879x over previous
#include <cuda_runtime.h>
#include <cstdint>

#define NNODES 50000

// ---------------- scratch (__device__ globals; no allocation) ----------------
// g_acc layout: [cnt: N floats][s1: N*96][s2: N*48]  -> single memset target
__device__ float g_acc[(size_t)NNODES * (1 + 96 + 48)];
__device__ float g_xl [(size_t)NNODES * 96];   // x  @ w1_l.T
__device__ float g_h1 [(size_t)NNODES * 96];   // layer-1 self term (pre-relu)
__device__ float g_h1l[(size_t)NNODES * 48];   // h1 @ w2_l.T
__device__ float g_wt1[96 * 192];              // transposed combined [k][o] (w1_l | w1_r)
__device__ float g_wt2[96 * 96];               // transposed combined [k][o] (w2_l | w2_r)

// ---------------- atomics ----------------
__device__ __forceinline__ void red_add_v4(float4* p, float4 v) {
    asm volatile("red.global.add.v4.f32 [%0], {%1, %2, %3, %4};"
                 :: "l"(p), "f"(v.x), "f"(v.y), "f"(v.z), "f"(v.w) : "memory");
}
__device__ __forceinline__ void red_add_f(float* p, float v) {
    asm volatile("red.global.add.f32 [%0], %1;" :: "l"(p), "f"(v) : "memory");
}

// ---------------- f32x2 packed FMA (sm_103a; PTX-only) ----------------
__device__ __forceinline__ unsigned long long pack2(float x, float y) {
    unsigned long long r;
    asm("mov.b64 %0, {%1, %2};" : "=l"(r) : "f"(x), "f"(y));
    return r;
}
__device__ __forceinline__ unsigned long long ffma2(unsigned long long a,
                                                    unsigned long long b,
                                                    unsigned long long c) {
    unsigned long long d;
    asm("fma.rn.f32x2 %0, %1, %2, %3;" : "=l"(d) : "l"(a), "l"(b), "l"(c));
    return d;
}

// ---------------- weight pre-transpose (tiny, once per launch) ----------------
__global__ void prep_weights(const float* __restrict__ w1l, const float* __restrict__ w1r,
                             const float* __restrict__ w2l, const float* __restrict__ w2r) {
    int tid = blockIdx.x * blockDim.x + threadIdx.x;
    int stride = blockDim.x * gridDim.x;
    for (int i = tid; i < 96 * 96; i += stride) {
        int o = i / 96, k = i % 96;
        g_wt1[k * 192 + o]      = w1l[i];
        g_wt1[k * 192 + 96 + o] = w1r[i];
    }
    for (int i = tid; i < 48 * 96; i += stride) {
        int o = i / 96, k = i % 96;
        g_wt2[k * 96 + o]      = w2l[i];
        g_wt2[k * 96 + 48 + o] = w2r[i];
    }
}

// ---------------- fused dual-output GEMM with FFMA2 ----------------
// Input dim fixed at 96. NP = f32x2 pairs/lane (192->3, 96->1); OUT=96 adds one
// scalar column per lane (col 64*NP+lane, always in the outb half).
// FUSE: staging computes relu(aggs*inv_cnt + xin) per element (layer-2 input).
template<int OUT, bool FUSE>
__global__ void gemm_k(const float* __restrict__ xin, const float* __restrict__ aggs,
                       const float* __restrict__ cnt,
                       const float* __restrict__ wt, const float* __restrict__ bias,
                       float* __restrict__ outa, float* __restrict__ outb, int nrows) {
    constexpr int  NP   = OUT / 64;
    constexpr bool SC   = (OUT % 64) != 0;
    constexpr int  HALF = OUT / 2;
    extern __shared__ float sm[];
    float* wTs = sm;              // 96*OUT
    float* xs  = sm + 96 * OUT;   // 64*96 row-major
    const int tid = threadIdx.x;

    for (int f = tid; f < 96 * OUT / 4; f += 256)
        ((float4*)wTs)[f] = ((const float4*)wt)[f];

    const int row0 = blockIdx.x * 64;
    for (int f = tid; f < 64 * 24; f += 256) {
        int r = f / 24, c = f % 24;
        int row = row0 + r;
        float4 v = make_float4(0.f, 0.f, 0.f, 0.f);
        if (row < nrows) {
            if (FUSE) {
                float inv = 1.0f / fmaxf(__ldg(&cnt[row]), 1.0f);
                float4 s = __ldg((const float4*)aggs + (size_t)row * 24 + c);
                float4 h = __ldg((const float4*)xin  + (size_t)row * 24 + c);
                v.x = fmaxf(fmaf(s.x, inv, h.x), 0.f);
                v.y = fmaxf(fmaf(s.y, inv, h.y), 0.f);
                v.z = fmaxf(fmaf(s.z, inv, h.z), 0.f);
                v.w = fmaxf(fmaf(s.w, inv, h.w), 0.f);
            } else {
                v = __ldg((const float4*)xin + (size_t)row * 24 + c);
            }
        }
        ((float4*)xs)[f] = v;
    }
    __syncthreads();

    const int warp = tid >> 5, lane = tid & 31;
    const int rb = warp * 8;
    const int pc = lane * 2 * NP;

    unsigned long long acc2[8][NP];
    float accs[8];
#pragma unroll
    for (int m = 0; m < 8; m++) {
#pragma unroll
        for (int j = 0; j < NP; j++) acc2[m][j] = 0ull;
        accs[m] = 0.f;
    }

    const float* wp  = wTs + pc;
    const float* wsp = wTs + 64 * NP + lane;

#pragma unroll 2
    for (int k = 0; k < 96; k++) {
        unsigned long long w2[NP];
#pragma unroll
        for (int j = 0; j < NP; j++)
            w2[j] = *(const unsigned long long*)(wp + k * OUT + 2 * j);
        float ws = SC ? wsp[k * OUT] : 0.f;
#pragma unroll
        for (int m = 0; m < 8; m++) {
            float x = xs[(rb + m) * 96 + k];
            unsigned long long x2 = pack2(x, x);
#pragma unroll
            for (int j = 0; j < NP; j++) acc2[m][j] = ffma2(x2, w2[j], acc2[m][j]);
            if (SC) accs[m] = fmaf(x, ws, accs[m]);
        }
    }

#pragma unroll
    for (int m = 0; m < 8; m++) {
        int r = row0 + rb + m;
        if (r >= nrows) break;
#pragma unroll
        for (int j = 0; j < NP; j++) {
            int c = pc + 2 * j;                   // pairs never straddle HALF
            float2 v = *(float2*)&acc2[m][j];
            if (c < HALF) {
                *(float2*)(outa + (size_t)r * HALF + c) = v;
            } else {
                int cb = c - HALF;
                float2 bv = *(const float2*)(bias + cb);
                v.x += bv.x; v.y += bv.y;
                *(float2*)(outb + (size_t)r * HALF + cb) = v;
            }
        }
        if (SC) {
            int cb = 64 * NP + lane - HALF;
            outb[(size_t)r * HALF + cb] = accs[m] + __ldg(&bias[cb]);
        }
    }
}

// ---------------- edge scatter (warp-cooperative, vec4 red) — R5 exact -------
// CHUNKS = row float4 count (24 for 96 dims, 12 for 48). EPI = edges/iteration.
template<int CHUNKS, int EPI, bool COUNT>
__global__ void scatter_k(const int* __restrict__ ei, int E,
                          const float* __restrict__ feat, float* __restrict__ accv,
                          float* __restrict__ cnt) {
    int gw   = (blockIdx.x * blockDim.x + threadIdx.x) >> 5;
    int lane = threadIdx.x & 31;
    int base = gw * 32;
    if (base >= E) return;
    int nv = E - base; if (nv > 32) nv = 32;

    int s = 0, d = 0;
    if (lane < nv) {
        s = ei[base + lane];          // src row
        d = ei[E + base + lane];      // dst row
    }
    const int  sub    = lane / CHUNKS;
    const int  ch     = lane % CHUNKS;
    const bool active = lane < EPI * CHUNKS;
    const float4* f4 = (const float4*)feat;
    float4*       a4 = (float4*)accv;

    for (int j = 0; j < nv; j += EPI) {
        int jj = active ? (j + sub) : j;
        bool ok = jj < nv;
        int ss = __shfl_sync(0xffffffffu, s, jj & 31);
        int dd = __shfl_sync(0xffffffffu, d, jj & 31);
        if (active && ok) {
            float4 v = __ldg(f4 + (size_t)ss * CHUNKS + ch);
            red_add_v4(a4 + (size_t)dd * CHUNKS + ch, v);
        }
        if (COUNT && lane == EPI * CHUNKS && ok)
            red_add_f(cnt + dd, 1.0f);
    }
}

// ---------------- finalize layer 2 ----------------
__global__ void fin2_k(float* __restrict__ out, int n) {  // n = N*12
    int idx = blockIdx.x * blockDim.x + threadIdx.x;
    if (idx >= n) return;
    int i = idx / 12;
    float inv = 1.0f / fmaxf(g_acc[i], 1.0f);
    const float4* s2 = (const float4*)(g_acc + (size_t)NNODES * 97);
    float4 s = s2[idx];
    float4 o = ((float4*)out)[idx];
    o.x = fmaf(s.x, inv, o.x);
    o.y = fmaf(s.y, inv, o.y);
    o.z = fmaf(s.z, inv, o.z);
    o.w = fmaf(s.w, inv, o.w);
    ((float4*)out)[idx] = o;
}

// ---------------- launch ----------------
extern "C" void kernel_launch(void* const* d_in, const int* in_sizes, int n_in,
                              void* d_out, int out_size) {
    const float* x   = (const float*)d_in[0];
    const int*   ei  = (const int*)d_in[1];     // int32 (JAX x64 disabled)
    const float* w1l = (const float*)d_in[2];
    const float* b1  = (const float*)d_in[3];
    const float* w1r = (const float*)d_in[4];
    const float* w2l = (const float*)d_in[5];
    const float* b2  = (const float*)d_in[6];
    const float* w2r = (const float*)d_in[7];
    float*       out = (float*)d_out;

    const int N = in_sizes[0] / 96;     // 50000
    const int E = in_sizes[1] / 2;      // 800000

    void *p_acc, *p_xl, *p_h1, *p_h1l, *p_wt1, *p_wt2;
    cudaGetSymbolAddress(&p_acc, g_acc);
    cudaGetSymbolAddress(&p_xl,  g_xl);
    cudaGetSymbolAddress(&p_h1,  g_h1);
    cudaGetSymbolAddress(&p_h1l, g_h1l);
    cudaGetSymbolAddress(&p_wt1, g_wt1);
    cudaGetSymbolAddress(&p_wt2, g_wt2);

    float* cnt = (float*)p_acc;
    float* s1  = cnt + NNODES;
    float* s2  = cnt + (size_t)NNODES * 97;

    static bool attr_done = false;
    if (!attr_done) {
        cudaFuncSetAttribute(gemm_k<192, false>,
                             cudaFuncAttributeMaxDynamicSharedMemorySize,
                             (96 * 192 + 64 * 96) * 4);
        cudaFuncSetAttribute(gemm_k<96, true>,
                             cudaFuncAttributeMaxDynamicSharedMemorySize,
                             (96 * 96 + 64 * 96) * 4);
        attr_done = true;
    }

    // zero cnt | s1 | s2 in one memset node
    cudaMemsetAsync(p_acc, 0, sizeof(float) * (size_t)NNODES * 145, 0);

    prep_weights<<<64, 256>>>(w1l, w1r, w2l, w2r);

    const int gemm_blocks = (N + 63) / 64;
    const int edge_warps  = (E + 31) / 32;
    const int edge_blocks = (edge_warps + 7) / 8;

    // layer 1: xl = x @ w1_l.T ; h1 = x @ w1_r.T + b1  (self term)
    gemm_k<192, false><<<gemm_blocks, 256, (96 * 192 + 64 * 96) * 4>>>(
        x, nullptr, nullptr, (const float*)p_wt1, b1,
        (float*)p_xl, (float*)p_h1, N);

    // s1 += xl[src] per edge; cnt[dst] += 1
    scatter_k<24, 1, true><<<edge_blocks, 256>>>(ei, E, (const float*)p_xl, s1, cnt);

    // layer 2 (fused fin1 staging): z = relu(s1/cnt + h1)
    // h1l = z @ w2_l.T ; out = z @ w2_r.T + b2
    gemm_k<96, true><<<gemm_blocks, 256, (96 * 96 + 64 * 96) * 4>>>(
        (const float*)p_h1, s1, cnt, (const float*)p_wt2, b2,
        (float*)p_h1l, out, N);

    // s2 += h1l[src] per edge
    scatter_k<12, 2, false><<<edge_blocks, 256>>>(ei, E, (const float*)p_h1l, s2, nullptr);

    // out += s2/cnt
    fin2_k<<<(N * 12 + 255) / 256, 256>>>(out, N * 12);
}